// round 2
// baseline (speedup 1.0000x reference)
#include <cuda_runtime.h>
#include <math.h>

// Tree-LSTM, 4-ary, depth 8. E=H=128, A=4. N_NODES = 87381, leaves = 65536.
// Level-major layout: level 8 (leaves) at node offset 0, then level 7, ... level 0.
// Children of level-l node j are level-(l+1) nodes 4j..4j+3 -> contiguous 512-float
// h/c rows. Output: out_h [87381*128] then out_c [87381*128].

#define NN     87381
#define NLEAF  65536

// ---------------- scratch (__device__ globals; no allocation allowed) ----------------
__device__ float g_Y[(size_t)NLEAF * 512];   // GEMM output scratch (128 MB; inner levels need <=16384*896)
__device__ float g_M[896 * 640];             // combined inner weight: rows 0..383 = [W_iou|U_iou], 384..895 = [W_f tiled | U_f]
__device__ float g_bias[896];                // combined inner bias
__device__ float g_Mleaf[512 * 128];         // leaf weight: rows 0..383 = W_iou, 384..511 = W_f
__device__ float g_bleaf[512];               // leaf bias: 0..383 = U_iou@h0 + b_iou + b_uiou, 384..511 = b_wf
__device__ float g_cuf[512];                 // leaf f-gate const: U_f@h0 + b_uf

__device__ __forceinline__ float sigf(float x) { return 1.0f / (1.0f + expf(-x)); }

// ---------------- prep: build combined weights ----------------
__global__ void prep_M_kernel(const float* __restrict__ W_iou, const float* __restrict__ U_iou,
                              const float* __restrict__ b_iou, const float* __restrict__ b_uiou,
                              const float* __restrict__ W_f,  const float* __restrict__ U_f,
                              const float* __restrict__ b_wf, const float* __restrict__ b_uf) {
    int stride = gridDim.x * blockDim.x;
    int idx = blockIdx.x * blockDim.x + threadIdx.x;
    for (int t = idx; t < 896 * 640; t += stride) {
        int c = t / 640, k = t - c * 640;
        float v;
        if (c < 384) {
            v = (k < 128) ? W_iou[c * 128 + k] : U_iou[c * 512 + (k - 128)];
        } else {
            int cc = c - 384;                       // 0..511 = a*128 + r
            v = (k < 128) ? W_f[(cc & 127) * 128 + k] : U_f[cc * 512 + (k - 128)];
        }
        g_M[t] = v;
    }
    for (int t = idx; t < 512 * 128; t += stride) {
        int c = t >> 7, k = t & 127;
        g_Mleaf[t] = (c < 384) ? W_iou[t] : W_f[(c - 384) * 128 + k];
    }
    if (idx < 896) {
        g_bias[idx] = (idx < 384) ? (b_iou[idx] + b_uiou[idx])
                                  : (b_wf[(idx - 384) & 127] + b_uf[idx - 384]);
    }
}

// leaf h-side constants: const_iou (into g_bleaf[0:384]) and const_uf (g_cuf)
__global__ void prep_const_kernel(const float* __restrict__ U_iou, const float* __restrict__ b_iou,
                                  const float* __restrict__ b_uiou, const float* __restrict__ U_f,
                                  const float* __restrict__ b_uf, const float* __restrict__ h0,
                                  const float* __restrict__ b_wf) {
    int c = blockIdx.x * blockDim.x + threadIdx.x;   // 0..895
    if (c < 384) {
        float s = b_iou[c] + b_uiou[c];
        for (int k = 0; k < 512; k++) s += U_iou[c * 512 + k] * h0[k];
        g_bleaf[c] = s;
    } else if (c < 896) {
        int cc = c - 384;                            // 0..511
        float s = b_uf[cc];
        for (int k = 0; k < 512; k++) s += U_f[cc * 512 + k] * h0[k];
        g_cuf[cc] = s;
        if (cc < 128) g_bleaf[384 + cc] = b_wf[cc];
    }
}

// ---------------- GEMM: Y[n x C] = Z[n x K] @ M^T + bias, Z row = [x(128) | hcat(512)] ----------------
// 64x64 tile, 256 threads, 4x4 micro-tile, K-chunk 16. C is always a multiple of 64.
__global__ void gemm_kernel(const float* __restrict__ X, const float* __restrict__ Hp,
                            int n, int K, int C, int useLeaf) {
    const float* __restrict__ M    = useLeaf ? g_Mleaf : g_M;
    const float* __restrict__ bias = useLeaf ? g_bleaf : g_bias;
    __shared__ __align__(16) float As[16][68];
    __shared__ __align__(16) float Bs[16][68];

    int tid = threadIdx.x;
    int rowBase = blockIdx.y * 64;
    int colBase = blockIdx.x * 64;
    int lr  = tid >> 2;            // 0..63 (row / col being loaded)
    int kk4 = (tid & 3) * 4;       // 0,4,8,12
    int tx = tid & 15, ty = tid >> 4;

    float acc[4][4];
#pragma unroll
    for (int i = 0; i < 4; i++)
#pragma unroll
        for (int j = 0; j < 4; j++) acc[i][j] = 0.f;

    for (int k0 = 0; k0 < K; k0 += 16) {
        // load A tile (64 rows x 16 k). k<128 comes from embeddings, k>=128 from prev-level h.
        int row = rowBase + lr;
        float4 av = make_float4(0.f, 0.f, 0.f, 0.f);
        if (row < n) {
            int k = k0 + kk4;      // chunk never straddles the 128 boundary (both multiples of 16)
            const float* src = (k < 128) ? (X + (size_t)row * 128 + k)
                                         : (Hp + (size_t)row * 512 + (k - 128));
            av = *(const float4*)src;
        }
        As[kk4 + 0][lr] = av.x; As[kk4 + 1][lr] = av.y;
        As[kk4 + 2][lr] = av.z; As[kk4 + 3][lr] = av.w;

        // load B tile (64 cols x 16 k); C multiple of 64 -> no col guard
        int c = colBase + lr;
        float4 bv = *(const float4*)(M + (size_t)c * K + k0 + kk4);
        Bs[kk4 + 0][lr] = bv.x; Bs[kk4 + 1][lr] = bv.y;
        Bs[kk4 + 2][lr] = bv.z; Bs[kk4 + 3][lr] = bv.w;
        __syncthreads();

#pragma unroll
        for (int kk = 0; kk < 16; kk++) {
            float4 a = *(const float4*)&As[kk][ty * 4];
            float4 b = *(const float4*)&Bs[kk][tx * 4];
            acc[0][0] += a.x * b.x; acc[0][1] += a.x * b.y; acc[0][2] += a.x * b.z; acc[0][3] += a.x * b.w;
            acc[1][0] += a.y * b.x; acc[1][1] += a.y * b.y; acc[1][2] += a.y * b.z; acc[1][3] += a.y * b.w;
            acc[2][0] += a.z * b.x; acc[2][1] += a.z * b.y; acc[2][2] += a.z * b.z; acc[2][3] += a.z * b.w;
            acc[3][0] += a.w * b.x; acc[3][1] += a.w * b.y; acc[3][2] += a.w * b.z; acc[3][3] += a.w * b.w;
        }
        __syncthreads();
    }

#pragma unroll
    for (int i = 0; i < 4; i++) {
        int row = rowBase + ty * 4 + i;
        if (row < n) {
#pragma unroll
            for (int j = 0; j < 4; j++) {
                int c = colBase + tx * 4 + j;
                g_Y[(size_t)row * C + c] = acc[i][j] + bias[c];
            }
        }
    }
}

// ---------------- elementwise: leaf level (shared h0/c0; Y cols: iou(384) + wf(128)) ----------------
__global__ void leaf_elem_kernel(const float* __restrict__ c0,
                                 float* __restrict__ out_h, float* __restrict__ out_c) {
    int j = blockIdx.x;
    int r = threadIdx.x;
    const float* Yr = g_Y + (size_t)j * 512;
    float iv = Yr[r], ov = Yr[128 + r], uv = Yr[256 + r], wf = Yr[384 + r];
    float c = sigf(iv) * tanhf(uv);
#pragma unroll
    for (int a = 0; a < 4; a++)
        c += sigf(wf + g_cuf[a * 128 + r]) * c0[a * 128 + r];
    float h = sigf(ov) * tanhf(c);
    out_h[(size_t)j * 128 + r] = h;
    out_c[(size_t)j * 128 + r] = c;
}

// ---------------- elementwise: inner levels (Y cols: iou(384) + fpre(512)) ----------------
__global__ void inner_elem_kernel(const float* __restrict__ cprev,
                                  float* __restrict__ out_h, float* __restrict__ out_c, int n) {
    int j = blockIdx.x;
    if (j >= n) return;
    int r = threadIdx.x;
    const float* Yr = g_Y + (size_t)j * 896;
    float iv = Yr[r], ov = Yr[128 + r], uv = Yr[256 + r];
    float c = sigf(iv) * tanhf(uv);
#pragma unroll
    for (int a = 0; a < 4; a++)
        c += sigf(Yr[384 + a * 128 + r]) * cprev[(size_t)(4 * j + a) * 128 + r];
    float h = sigf(ov) * tanhf(c);
    out_h[(size_t)j * 128 + r] = h;
    out_c[(size_t)j * 128 + r] = c;
}

// ---------------- launch ----------------
extern "C" void kernel_launch(void* const* d_in, const int* in_sizes, int n_in,
                              void* d_out, int out_size) {
    const float* emb    = (const float*)d_in[0];
    const float* W_iou  = (const float*)d_in[1];
    const float* b_iou  = (const float*)d_in[2];
    const float* U_iou  = (const float*)d_in[3];
    const float* b_uiou = (const float*)d_in[4];
    const float* W_f    = (const float*)d_in[5];
    const float* b_wf   = (const float*)d_in[6];
    const float* U_f    = (const float*)d_in[7];
    const float* b_uf   = (const float*)d_in[8];
    const float* h0     = (const float*)d_in[9];
    const float* c0     = (const float*)d_in[10];

    float* out_h = (float*)d_out;
    float* out_c = out_h + (size_t)NN * 128;

    prep_M_kernel<<<512, 256>>>(W_iou, U_iou, b_iou, b_uiou, W_f, U_f, b_wf, b_uf);
    prep_const_kernel<<<7, 128>>>(U_iou, b_iou, b_uiou, U_f, b_uf, h0, b_wf);

    // level sizes, leaves first
    const int lev_n[9] = {65536, 16384, 4096, 1024, 256, 64, 16, 4, 1};
    int offs[10];
    offs[0] = 0;
    for (int i = 0; i < 9; i++) offs[i + 1] = offs[i] + lev_n[i];

    // leaf level: Y = X @ Mleaf^T + bleaf  (C=512), then gates with shared h0/c0 constants
    gemm_kernel<<<dim3(512 / 64, NLEAF / 64), 256>>>(emb, nullptr, NLEAF, 128, 512, 1);
    leaf_elem_kernel<<<NLEAF, 128>>>(c0, out_h, out_c);

    // inner levels 7..0
    for (int i = 1; i < 9; i++) {
        int n = lev_n[i];
        const float* X  = emb   + (size_t)offs[i]     * 128;
        const float* Hp = out_h + (size_t)offs[i - 1] * 128;  // children h (contiguous 512/row)
        const float* Cp = out_c + (size_t)offs[i - 1] * 128;  // children c
        gemm_kernel<<<dim3(896 / 64, (n + 63) / 64), 256>>>(X, Hp, n, 640, 896, 0);
        inner_elem_kernel<<<n, 128>>>(Cp, out_h + (size_t)offs[i] * 128,
                                      out_c + (size_t)offs[i] * 128, n);
    }
}

// round 4
// speedup vs baseline: 2.1828x; 2.1828x over previous
#include <cuda_runtime.h>
#include <math.h>
#include <stdint.h>

// Tree-LSTM, 4-ary, depth 8. E=H=128, A=4. N_NODES=87381, leaves=65536.
// R4: tf32 mma.sync (HMMA) GEMMs — tcgen05 is unavailable (harness PTX targets
// compute_103 without the 'a' feature set). CTA tile 128x128, warp tile 64x32.

#define NN     87381
#define NLEAF  65536

// ---------------- scratch ----------------
__device__ float g_Y[(size_t)NLEAF * 512];   // leaf: 65536x512; inner max 16384x896 (smaller)
__device__ float g_M[896 * 640];             // inner combined weight (tf32-rounded)
__device__ float g_bias[896];
__device__ float g_Mleaf[512 * 128];         // leaf weight (tf32-rounded)
__device__ float g_bleaf[512];               // leaf bias (iou consts + b_wf)
__device__ float g_cuf[512];                 // leaf f-gate const U_f@h0+b_uf

__device__ __forceinline__ float sigf(float x) { return 1.0f / (1.0f + expf(-x)); }
__device__ __forceinline__ uint32_t f2tf(float f) {
    uint32_t r; asm("cvt.rna.tf32.f32 %0, %1;" : "=r"(r) : "f"(f)); return r;
}

// ---------------- prep ----------------
__global__ void prep_M_kernel(const float* __restrict__ W_iou, const float* __restrict__ U_iou,
                              const float* __restrict__ b_iou, const float* __restrict__ b_uiou,
                              const float* __restrict__ W_f,  const float* __restrict__ U_f,
                              const float* __restrict__ b_wf, const float* __restrict__ b_uf) {
    int stride = gridDim.x * blockDim.x;
    int idx = blockIdx.x * blockDim.x + threadIdx.x;
    for (int t = idx; t < 896 * 640; t += stride) {
        int c = t / 640, k = t - c * 640;
        float v;
        if (c < 384) v = (k < 128) ? W_iou[c * 128 + k] : U_iou[c * 512 + (k - 128)];
        else {
            int cc = c - 384;
            v = (k < 128) ? W_f[(cc & 127) * 128 + k] : U_f[cc * 512 + (k - 128)];
        }
        g_M[t] = __uint_as_float(f2tf(v));
    }
    for (int t = idx; t < 512 * 128; t += stride) {
        int c = t >> 7, k = t & 127;
        float v = (c < 384) ? W_iou[t] : W_f[(c - 384) * 128 + k];
        g_Mleaf[t] = __uint_as_float(f2tf(v));
    }
    if (idx < 896)
        g_bias[idx] = (idx < 384) ? (b_iou[idx] + b_uiou[idx])
                                  : (b_wf[(idx - 384) & 127] + b_uf[idx - 384]);
}

__global__ void prep_const_kernel(const float* __restrict__ U_iou, const float* __restrict__ b_iou,
                                  const float* __restrict__ b_uiou, const float* __restrict__ U_f,
                                  const float* __restrict__ b_uf, const float* __restrict__ h0,
                                  const float* __restrict__ b_wf) {
    int c = blockIdx.x * blockDim.x + threadIdx.x;
    if (c < 384) {
        float s = b_iou[c] + b_uiou[c];
        for (int k = 0; k < 512; k++) s += U_iou[c * 512 + k] * h0[k];
        g_bleaf[c] = s;
    } else if (c < 896) {
        int cc = c - 384;
        float s = b_uf[cc];
        for (int k = 0; k < 512; k++) s += U_f[cc * 512 + k] * h0[k];
        g_cuf[cc] = s;
        if (cc < 128) g_bleaf[384 + cc] = b_wf[cc];
    }
}

// ---------------- HMMA tf32 GEMM: Y[n x C] = Z[n x K] @ M^T + bias ----------------
// Z row = [x(128) | hcat(512)]. CTA 128x128, 8 warps (2 row-groups x 4 col-groups),
// warp tile 64x32 = 4x4 mma.m16n8k8 tiles. K-chunk 32 in smem, pitch 36 (conflict-free).
__device__ __forceinline__ void mma_tf32(float* c, const uint32_t* a, const uint32_t* b) {
    asm volatile(
        "mma.sync.aligned.m16n8k8.row.col.f32.tf32.tf32.f32 "
        "{%0,%1,%2,%3}, {%4,%5,%6,%7}, {%8,%9}, {%0,%1,%2,%3};"
        : "+f"(c[0]), "+f"(c[1]), "+f"(c[2]), "+f"(c[3])
        : "r"(a[0]), "r"(a[1]), "r"(a[2]), "r"(a[3]), "r"(b[0]), "r"(b[1]));
}

__global__ void __launch_bounds__(256)
gemm_tc(const float* __restrict__ X, const float* __restrict__ Hp,
        int n, int K, int C, int leaf) {
    const float* __restrict__ M    = leaf ? g_Mleaf : g_M;
    const float* __restrict__ bias = leaf ? g_bleaf : g_bias;
    __shared__ float As[128][36];
    __shared__ float Bs[128][36];

    int tid = threadIdx.x, wid = tid >> 5, lane = tid & 31;
    int gid = lane >> 2, tig = lane & 3;
    int wr = wid >> 2, wc = wid & 3;
    int rowBase = blockIdx.y * 128, colBase = blockIdx.x * 128;

    float acc[4][4][4];
#pragma unroll
    for (int mi = 0; mi < 4; mi++)
#pragma unroll
        for (int ni = 0; ni < 4; ni++)
#pragma unroll
            for (int q = 0; q < 4; q++) acc[mi][ni][q] = 0.f;

    for (int k0 = 0; k0 < K; k0 += 32) {
        // ---- stage A (128 rows x 32 k), tf32-rounded ----
        const float* base; int pitch, koff;
        if (k0 < 128) { base = X;  pitch = 128; koff = k0; }
        else          { base = Hp; pitch = 512; koff = k0 - 128; }
#pragma unroll
        for (int it = tid; it < 1024; it += 256) {
            int r = it >> 3, q = it & 7;
            int row = rowBase + r;
            float4 v = make_float4(0.f, 0.f, 0.f, 0.f);
            if (row < n) v = *(const float4*)(base + (size_t)row * pitch + koff + q * 4);
            float4 u;
            u.x = __uint_as_float(f2tf(v.x)); u.y = __uint_as_float(f2tf(v.y));
            u.z = __uint_as_float(f2tf(v.z)); u.w = __uint_as_float(f2tf(v.w));
            *(float4*)&As[r][q * 4] = u;
        }
        // ---- stage B (128 cols x 32 k), already rounded ----
#pragma unroll
        for (int it = tid; it < 1024; it += 256) {
            int r = it >> 3, q = it & 7;
            float4 v = *(const float4*)(M + (size_t)(colBase + r) * K + k0 + q * 4);
            *(float4*)&Bs[r][q * 4] = v;
        }
        __syncthreads();

#pragma unroll
        for (int ks = 0; ks < 32; ks += 8) {
            uint32_t a[4][4], b[4][2];
#pragma unroll
            for (int mi = 0; mi < 4; mi++) {
                int r0 = wr * 64 + mi * 16 + gid;
                a[mi][0] = __float_as_uint(As[r0][ks + tig]);
                a[mi][1] = __float_as_uint(As[r0 + 8][ks + tig]);
                a[mi][2] = __float_as_uint(As[r0][ks + tig + 4]);
                a[mi][3] = __float_as_uint(As[r0 + 8][ks + tig + 4]);
            }
#pragma unroll
            for (int ni = 0; ni < 4; ni++) {
                int c0 = wc * 32 + ni * 8 + gid;
                b[ni][0] = __float_as_uint(Bs[c0][ks + tig]);
                b[ni][1] = __float_as_uint(Bs[c0][ks + tig + 4]);
            }
#pragma unroll
            for (int mi = 0; mi < 4; mi++)
#pragma unroll
                for (int ni = 0; ni < 4; ni++)
                    mma_tf32(acc[mi][ni], a[mi], b[ni]);
        }
        __syncthreads();
    }

    // ---- store with bias ----
#pragma unroll
    for (int mi = 0; mi < 4; mi++) {
        int row0 = rowBase + wr * 64 + mi * 16 + gid;
#pragma unroll
        for (int ni = 0; ni < 4; ni++) {
            int col = colBase + wc * 32 + ni * 8 + tig * 2;
            float bx = bias[col], by = bias[col + 1];
            if (row0 < n) {
                float2 o = make_float2(acc[mi][ni][0] + bx, acc[mi][ni][1] + by);
                *(float2*)&g_Y[(size_t)row0 * C + col] = o;
            }
            if (row0 + 8 < n) {
                float2 o = make_float2(acc[mi][ni][2] + bx, acc[mi][ni][3] + by);
                *(float2*)&g_Y[(size_t)(row0 + 8) * C + col] = o;
            }
        }
    }
}

// ---------------- elementwise: leaf level ----------------
__global__ void leaf_elem_kernel(const float* __restrict__ c0,
                                 float* __restrict__ out_h, float* __restrict__ out_c) {
    int j = blockIdx.x;
    int r = threadIdx.x;
    const float* Yr = g_Y + (size_t)j * 512;
    float iv = Yr[r], ov = Yr[128 + r], uv = Yr[256 + r], wf = Yr[384 + r];
    float c = sigf(iv) * tanhf(uv);
#pragma unroll
    for (int a = 0; a < 4; a++)
        c += sigf(wf + g_cuf[a * 128 + r]) * c0[a * 128 + r];
    float h = sigf(ov) * tanhf(c);
    out_h[(size_t)j * 128 + r] = h;
    out_c[(size_t)j * 128 + r] = c;
}

// ---------------- elementwise: inner levels ----------------
__global__ void inner_elem_kernel(const float* __restrict__ cprev,
                                  float* __restrict__ out_h, float* __restrict__ out_c, int n) {
    int j = blockIdx.x;
    if (j >= n) return;
    int r = threadIdx.x;
    const float* Yr = g_Y + (size_t)j * 896;
    float iv = Yr[r], ov = Yr[128 + r], uv = Yr[256 + r];
    float c = sigf(iv) * tanhf(uv);
#pragma unroll
    for (int a = 0; a < 4; a++)
        c += sigf(Yr[384 + a * 128 + r]) * cprev[(size_t)(4 * j + a) * 128 + r];
    float h = sigf(ov) * tanhf(c);
    out_h[(size_t)j * 128 + r] = h;
    out_c[(size_t)j * 128 + r] = c;
}

// ---------------- launch ----------------
extern "C" void kernel_launch(void* const* d_in, const int* in_sizes, int n_in,
                              void* d_out, int out_size) {
    const float* emb    = (const float*)d_in[0];
    const float* W_iou  = (const float*)d_in[1];
    const float* b_iou  = (const float*)d_in[2];
    const float* U_iou  = (const float*)d_in[3];
    const float* b_uiou = (const float*)d_in[4];
    const float* W_f    = (const float*)d_in[5];
    const float* b_wf   = (const float*)d_in[6];
    const float* U_f    = (const float*)d_in[7];
    const float* b_uf   = (const float*)d_in[8];
    const float* h0     = (const float*)d_in[9];
    const float* c0     = (const float*)d_in[10];

    float* out_h = (float*)d_out;
    float* out_c = out_h + (size_t)NN * 128;

    prep_M_kernel<<<512, 256>>>(W_iou, U_iou, b_iou, b_uiou, W_f, U_f, b_wf, b_uf);
    prep_const_kernel<<<7, 128>>>(U_iou, b_iou, b_uiou, U_f, b_uf, h0, b_wf);

    const int lev_n[9] = {65536, 16384, 4096, 1024, 256, 64, 16, 4, 1};
    int offs[10];
    offs[0] = 0;
    for (int i = 0; i < 9; i++) offs[i + 1] = offs[i] + lev_n[i];

    // leaf level: HMMA GEMM (C=512, K=128) + gates
    gemm_tc<<<dim3(4, NLEAF / 128), 256>>>(emb, nullptr, NLEAF, 128, 512, 1);
    leaf_elem_kernel<<<NLEAF, 128>>>(c0, out_h, out_c);

    // inner levels 7..0 (C=896, K=640)
    for (int i = 1; i < 9; i++) {
        int n = lev_n[i];
        const float* X  = emb   + (size_t)offs[i]     * 128;
        const float* Hp = out_h + (size_t)offs[i - 1] * 128;
        const float* Cp = out_c + (size_t)offs[i - 1] * 128;
        gemm_tc<<<dim3(7, (n + 127) / 128), 256>>>(X, Hp, n, 640, 896, 0);
        inner_elem_kernel<<<n, 128>>>(Cp, out_h + (size_t)offs[i] * 128,
                                      out_c + (size_t)offs[i] * 128, n);
    }
}